// round 2
// baseline (speedup 1.0000x reference)
#include <cuda_runtime.h>
#include <cuda_bf16.h>

#define NB 8
#define NPTS 16384
#define NQ 1024
#define NC 64
#define NS 32
#define R2 0.04f
#define WPB 8   // warps per block (main kernel)

// 32 MB scratch: features transposed to (B, N, C) so each point's channel
// vector is a contiguous 256B row.
__device__ float g_feats_t[(size_t)NB * NPTS * NC];

// ---- pre-pass: tiled transpose (B,C,N) -> (B,N,C) ----
__global__ __launch_bounds__(256) void transpose_kernel(const float* __restrict__ feats) {
    __shared__ float tile[32][33];
    const int b  = blockIdx.z;
    const int c0 = blockIdx.y * 32;
    const int n0 = blockIdx.x * 32;
    const int tx = threadIdx.x, ty = threadIdx.y;

    const float* src = feats + ((size_t)b * NC + c0) * NPTS + n0;
    #pragma unroll
    for (int k = 0; k < 32; k += 8)
        tile[ty + k][tx] = src[(size_t)(ty + k) * NPTS + tx];
    __syncthreads();

    float* dst = g_feats_t + ((size_t)b * NPTS + n0) * NC + c0;
    #pragma unroll
    for (int k = 0; k < 32; k += 8)
        dst[(size_t)(ty + k) * NC + tx] = tile[tx][ty + k];
}

// ---- main: ball query (early-exit scan) + grouped gather ----
__global__ __launch_bounds__(WPB * 32) void qag_kernel(
    const float* __restrict__ xyz,      // (B, N, 3)
    const float* __restrict__ new_xyz,  // (B, S, 3)
    float* __restrict__ out)            // (B, 3+C, S, NS)
{
    const int lane = threadIdx.x & 31;
    const int wid  = threadIdx.x >> 5;
    const int q = blockIdx.x * WPB + wid;      // global query id in [0, B*S)
    if (q >= NB * NQ) return;
    const int b = q / NQ;
    const int s = q % NQ;

    __shared__ int   idx_buf_all[WPB][NS];
    __shared__ float fsm_all[WPB][32 * 33];    // 32 channels x 32 samples (+pad)
    int*   idx_buf = idx_buf_all[wid];
    float* fsm     = fsm_all[wid];

    const float qx = new_xyz[q * 3 + 0];
    const float qy = new_xyz[q * 3 + 1];
    const float qz = new_xyz[q * 3 + 2];

    const float* xb = xyz + (size_t)b * NPTS * 3;

    // ---- ball query: sequential scan with early exit ----
    int cnt = 0;
    for (int j0 = 0; j0 < NPTS; j0 += 32) {
        const int j = j0 + lane;
        const float dx = xb[j * 3 + 0] - qx;
        const float dy = xb[j * 3 + 1] - qy;
        const float dz = xb[j * 3 + 2] - qz;
        const float d2 = dx * dx + dy * dy + dz * dz;
        const bool within = d2 < R2;
        const unsigned mask = __ballot_sync(0xFFFFFFFFu, within);
        if (within) {
            const int pos = cnt + __popc(mask & ((1u << lane) - 1u));
            if (pos < NS) idx_buf[pos] = j;
        }
        cnt += __popc(mask);
        if (cnt >= NS) break;   // uniform across warp
    }
    __syncwarp();
    const int eff = cnt < NS ? cnt : NS;
    int first = 0;
    if (eff > 0) first = idx_buf[0];
    __syncwarp();
    if (lane >= eff) idx_buf[lane] = first;   // pad with first valid (0 if none)
    __syncwarp();
    const int my = idx_buf[lane];             // lane k owns sample k

    // ---- grouped xyz (channels 0..2), coalesced writes ----
    const float px = xb[my * 3 + 0] - qx;
    const float py = xb[my * 3 + 1] - qy;
    const float pz = xb[my * 3 + 2] - qz;

    const size_t CH = (size_t)NQ * NS;                         // channel stride
    float* ob = out + ((size_t)b * (3 + NC) * NQ + s) * NS + lane;
    ob[0 * CH] = px;
    ob[1 * CH] = py;
    ob[2 * CH] = pz;

    // ---- grouped features: coalesced row gather + smem transpose ----
    const float* fb = g_feats_t + (size_t)b * NPTS * NC;
    float* of = ob + 3 * CH;
    #pragma unroll
    for (int cc = 0; cc < 2; ++cc) {
        // load: lane = channel (coalesced 128B per sample row)
        #pragma unroll 8
        for (int m = 0; m < NS; ++m) {
            const int im = idx_buf[m];
            fsm[lane * 33 + m] = fb[(size_t)im * NC + cc * 32 + lane];
        }
        __syncwarp();
        // store: lane = sample (coalesced 128B per channel)
        #pragma unroll
        for (int c = 0; c < 32; ++c) {
            of[(size_t)(cc * 32 + c) * CH] = fsm[c * 33 + lane];
        }
        __syncwarp();
    }
}

extern "C" void kernel_launch(void* const* d_in, const int* in_sizes, int n_in,
                              void* d_out, int out_size) {
    const float* xyz     = (const float*)d_in[0];
    const float* new_xyz = (const float*)d_in[1];
    const float* feats   = (const float*)d_in[2];
    float* out = (float*)d_out;

    dim3 tgrid(NPTS / 32, NC / 32, NB);
    transpose_kernel<<<tgrid, dim3(32, 8)>>>(feats);

    const int nq = NB * NQ;                 // 8192 queries, one warp each
    const int blocks = (nq + WPB - 1) / WPB;
    qag_kernel<<<blocks, WPB * 32>>>(xyz, new_xyz, out);
}

// round 3
// speedup vs baseline: 2.2209x; 2.2209x over previous
#include <cuda_runtime.h>
#include <cuda_bf16.h>

#define NB 8
#define NPTS 16384
#define NQ 1024
#define NC 64
#define NS 32
#define R2 0.04f
#define WPB 8   // warps per block (main kernel)

// 2 MB scratch: xyz packed as float4 (x,y,z,0) for single-LDG.128 scan loads.
__device__ float4 g_xyz4[(size_t)NB * NPTS];

// ---- pre-pass: pack (B,N,3) f32 -> (B,N) float4 ----
__global__ __launch_bounds__(256) void pack_xyz_kernel(const float* __restrict__ xyz) {
    __shared__ float sbuf[8][96];
    const int warp = threadIdx.x >> 5, lane = threadIdx.x & 31;
    const size_t base = (size_t)blockIdx.x * 256 + warp * 32;  // global point id
    const float* src = xyz + base * 3;
    float* s = sbuf[warp];
    s[lane]      = src[lane];
    s[lane + 32] = src[lane + 32];
    s[lane + 64] = src[lane + 64];
    __syncwarp();
    g_xyz4[base + lane] = make_float4(s[lane * 3], s[lane * 3 + 1], s[lane * 3 + 2], 0.f);
}

// ---- main: 4x-unrolled ball-query scan + grouped gather ----
__global__ __launch_bounds__(WPB * 32) void qag_kernel(
    const float* __restrict__ new_xyz,  // (B, S, 3)
    const float* __restrict__ feats,    // (B, C, N)
    float* __restrict__ out)            // (B, 3+C, S, NS)
{
    const int lane = threadIdx.x & 31;
    const int wid  = threadIdx.x >> 5;
    const int q = blockIdx.x * WPB + wid;      // global query id in [0, B*S)
    const int b = q / NQ;
    const int s = q % NQ;

    __shared__ int idx_buf_all[WPB][NS];
    int* idx_buf = idx_buf_all[wid];

    const float qx = new_xyz[q * 3 + 0];
    const float qy = new_xyz[q * 3 + 1];
    const float qz = new_xyz[q * 3 + 2];

    const float4* xb4 = g_xyz4 + (size_t)b * NPTS;
    const unsigned lt = (1u << lane) - 1u;

    // ---- ball query: chunks of 128 points, MLP=4, early exit per chunk ----
    int cnt = 0;
    for (int j0 = 0; j0 < NPTS; j0 += 128) {
        const float4 p0 = xb4[j0 + lane];
        const float4 p1 = xb4[j0 + 32 + lane];
        const float4 p2 = xb4[j0 + 64 + lane];
        const float4 p3 = xb4[j0 + 96 + lane];

        float dx, dy, dz;
        dx = p0.x - qx; dy = p0.y - qy; dz = p0.z - qz;
        const bool w0 = dx * dx + dy * dy + dz * dz < R2;
        dx = p1.x - qx; dy = p1.y - qy; dz = p1.z - qz;
        const bool w1 = dx * dx + dy * dy + dz * dz < R2;
        dx = p2.x - qx; dy = p2.y - qy; dz = p2.z - qz;
        const bool w2 = dx * dx + dy * dy + dz * dz < R2;
        dx = p3.x - qx; dy = p3.y - qy; dz = p3.z - qz;
        const bool w3 = dx * dx + dy * dy + dz * dz < R2;

        const unsigned m0 = __ballot_sync(0xFFFFFFFFu, w0);
        const unsigned m1 = __ballot_sync(0xFFFFFFFFu, w1);
        const unsigned m2 = __ballot_sync(0xFFFFFFFFu, w2);
        const unsigned m3 = __ballot_sync(0xFFFFFFFFu, w3);

        const int base0 = cnt;
        const int base1 = base0 + __popc(m0);
        const int base2 = base1 + __popc(m1);
        const int base3 = base2 + __popc(m2);
        cnt = base3 + __popc(m3);

        if (w0) { const int p = base0 + __popc(m0 & lt); if (p < NS) idx_buf[p] = j0 + lane; }
        if (w1) { const int p = base1 + __popc(m1 & lt); if (p < NS) idx_buf[p] = j0 + 32 + lane; }
        if (w2) { const int p = base2 + __popc(m2 & lt); if (p < NS) idx_buf[p] = j0 + 64 + lane; }
        if (w3) { const int p = base3 + __popc(m3 & lt); if (p < NS) idx_buf[p] = j0 + 96 + lane; }

        if (cnt >= NS) break;   // uniform across warp
    }
    __syncwarp();
    const int eff = cnt < NS ? cnt : NS;
    int first = 0;
    if (eff > 0) first = idx_buf[0];
    __syncwarp();
    if (lane >= eff) idx_buf[lane] = first;   // pad with first valid (0 if none)
    __syncwarp();
    const int my = idx_buf[lane];             // lane k owns sample k

    // ---- grouped xyz (channels 0..2), coalesced writes ----
    const float4 P = xb4[my];
    const size_t CH = (size_t)NQ * NS;                         // channel stride
    float* ob = out + ((size_t)b * (3 + NC) * NQ + s) * NS + lane;
    ob[0 * CH] = P.x - qx;
    ob[1 * CH] = P.y - qy;
    ob[2 * CH] = P.z - qz;

    // ---- grouped features (channels 3..66), scattered gather ----
    const float* fb = feats + (size_t)b * NC * NPTS + my;
    float* of = ob + 3 * CH;
    #pragma unroll 8
    for (int c = 0; c < NC; ++c) {
        of[c * CH] = __ldg(fb + (size_t)c * NPTS);
    }
}

extern "C" void kernel_launch(void* const* d_in, const int* in_sizes, int n_in,
                              void* d_out, int out_size) {
    const float* xyz     = (const float*)d_in[0];
    const float* new_xyz = (const float*)d_in[1];
    const float* feats   = (const float*)d_in[2];
    float* out = (float*)d_out;

    pack_xyz_kernel<<<(NB * NPTS) / 256, 256>>>(xyz);

    const int nq = NB * NQ;                 // 8192 queries, one warp each
    const int blocks = (nq + WPB - 1) / WPB;
    qag_kernel<<<blocks, WPB * 32>>>(new_xyz, feats, out);
}

// round 4
// speedup vs baseline: 2.2980x; 1.0347x over previous
#include <cuda_runtime.h>
#include <cuda_bf16.h>

#define NB 8
#define NPTS 16384
#define NQ 1024
#define NC 64
#define NS 32
#define R2 0.04f
#define WPB 4   // warps per block (main kernel)

// 2 MB scratch: xyz packed as float4 for single-LDG.128 scan loads.
__device__ float4 g_xyz4[(size_t)NB * NPTS];
// 33.5 MB scratch: features transposed to (B, N, C); fits in L2 (126 MB).
__device__ float g_feats_t[(size_t)NB * NPTS * NC];

// ---- pre-pass 1: pack (B,N,3) f32 -> (B,N) float4 ----
__global__ __launch_bounds__(256) void pack_xyz_kernel(const float* __restrict__ xyz) {
    __shared__ float sbuf[8][96];
    const int warp = threadIdx.x >> 5, lane = threadIdx.x & 31;
    const size_t base = (size_t)blockIdx.x * 256 + warp * 32;
    const float* src = xyz + base * 3;
    float* s = sbuf[warp];
    s[lane]      = src[lane];
    s[lane + 32] = src[lane + 32];
    s[lane + 64] = src[lane + 64];
    __syncwarp();
    g_xyz4[base + lane] = make_float4(s[lane * 3], s[lane * 3 + 1], s[lane * 3 + 2], 0.f);
}

// ---- pre-pass 2: transpose (B,C,N) -> (B,N,C), 32-point tiles ----
__global__ __launch_bounds__(256) void feat_transpose_kernel(const float* __restrict__ feats) {
    __shared__ float tile[32][65];       // [n][c], pad 65 -> conflict-free both phases
    const int b  = blockIdx.y;
    const int n0 = blockIdx.x * 32;
    const int t  = threadIdx.x;
    const int tx = t & 31;               // n within tile
    const int ty = t >> 5;               // c base (0..7)

    const float* src = feats + (size_t)b * NC * NPTS + n0;
    #pragma unroll
    for (int k = 0; k < 8; ++k) {
        const int c = ty * 8 + k;
        tile[tx][c] = src[(size_t)c * NPTS + tx];
    }
    __syncthreads();

    float* dst = g_feats_t + ((size_t)b * NPTS + n0) * NC;
    #pragma unroll
    for (int k = 0; k < 8; ++k) {
        const int idx = k * 256 + t;
        const int n = idx >> 6;          // idx / 64
        const int c = idx & 63;
        dst[(size_t)n * NC + c] = tile[n][c];
    }
}

// ---- main: 8x-unrolled ball-query scan + float4 grouped gather ----
__global__ __launch_bounds__(WPB * 32) void qag_kernel(
    const float* __restrict__ new_xyz,  // (B, S, 3)
    float* __restrict__ out)            // (B, 3+C, S, NS)
{
    const int lane = threadIdx.x & 31;
    const int wid  = threadIdx.x >> 5;
    const int q = blockIdx.x * WPB + wid;      // global query id in [0, B*S)
    const int b = q / NQ;
    const int s = q % NQ;

    __shared__ int idx_buf_all[WPB][NS];
    int* idx_buf = idx_buf_all[wid];

    const float qx = new_xyz[q * 3 + 0];
    const float qy = new_xyz[q * 3 + 1];
    const float qz = new_xyz[q * 3 + 2];

    const float4* xb4 = g_xyz4 + (size_t)b * NPTS;
    const unsigned lt = (1u << lane) - 1u;

    // ---- ball query: chunks of 256 points, MLP=8, early exit per chunk ----
    int cnt = 0;
    for (int j0 = 0; j0 < NPTS; j0 += 256) {
        float4 p[8];
        #pragma unroll
        for (int u = 0; u < 8; ++u) p[u] = xb4[j0 + u * 32 + lane];

        bool w[8];
        #pragma unroll
        for (int u = 0; u < 8; ++u) {
            const float dx = p[u].x - qx;
            const float dy = p[u].y - qy;
            const float dz = p[u].z - qz;
            w[u] = dx * dx + dy * dy + dz * dz < R2;
        }

        unsigned m[8];
        #pragma unroll
        for (int u = 0; u < 8; ++u) m[u] = __ballot_sync(0xFFFFFFFFu, w[u]);

        int base = cnt;
        #pragma unroll
        for (int u = 0; u < 8; ++u) {
            if (w[u]) {
                const int pos = base + __popc(m[u] & lt);
                if (pos < NS) idx_buf[pos] = j0 + u * 32 + lane;
            }
            base += __popc(m[u]);
        }
        cnt = base;
        if (cnt >= NS) break;   // uniform across warp
    }
    __syncwarp();
    const int eff = cnt < NS ? cnt : NS;
    int first = 0;
    if (eff > 0) first = idx_buf[0];
    __syncwarp();
    if (lane >= eff) idx_buf[lane] = first;   // pad with first valid (0 if none)
    __syncwarp();
    const int my = idx_buf[lane];             // lane k owns sample k

    // ---- grouped xyz (channels 0..2), coalesced writes ----
    const float4 P = xb4[my];
    const size_t CH = (size_t)NQ * NS;                         // channel stride
    float* ob = out + ((size_t)b * (3 + NC) * NQ + s) * NS + lane;
    ob[0 * CH] = P.x - qx;
    ob[1 * CH] = P.y - qy;
    ob[2 * CH] = P.z - qz;

    // ---- grouped features: float4 row gather, lane = sample ----
    // lane holds channels 4g..4g+3 of its own sample -> all 4 stores coalesced.
    const float4* fb = (const float4*)(g_feats_t + (size_t)b * NPTS * NC) + (size_t)my * (NC / 4);
    float* of = ob + 3 * CH;
    #pragma unroll 4
    for (int g = 0; g < NC / 4; ++g) {
        const float4 v = __ldg(fb + g);
        of[(size_t)(4 * g + 0) * CH] = v.x;
        of[(size_t)(4 * g + 1) * CH] = v.y;
        of[(size_t)(4 * g + 2) * CH] = v.z;
        of[(size_t)(4 * g + 3) * CH] = v.w;
    }
}

extern "C" void kernel_launch(void* const* d_in, const int* in_sizes, int n_in,
                              void* d_out, int out_size) {
    const float* xyz     = (const float*)d_in[0];
    const float* new_xyz = (const float*)d_in[1];
    const float* feats   = (const float*)d_in[2];
    float* out = (float*)d_out;

    pack_xyz_kernel<<<(NB * NPTS) / 256, 256>>>(xyz);
    feat_transpose_kernel<<<dim3(NPTS / 32, NB), 256>>>(feats);

    const int nq = NB * NQ;                 // 8192 queries, one warp each
    const int blocks = nq / WPB;
    qag_kernel<<<blocks, WPB * 32>>>(new_xyz, out);
}

// round 5
// speedup vs baseline: 2.3091x; 1.0048x over previous
#include <cuda_runtime.h>
#include <cuda_bf16.h>

#define NB 8
#define NPTS 16384
#define NQ 1024
#define NC 64
#define NS 32
#define R2 0.04f
#define WPB 4   // warps per block (main kernel)

// 2 MB scratch: xyz packed as float4 for single-LDG.128 scan loads.
__device__ float4 g_xyz4[(size_t)NB * NPTS];
// 33.5 MB scratch: features transposed to (B, N, C); fits in L2 (126 MB).
__device__ float g_feats_t[(size_t)NB * NPTS * NC];

#define TBLOCKS (NB * (NPTS / 32))      // 4096 transpose tiles
#define PBLOCKS ((NB * NPTS) / 256)     // 512 pack blocks

// ---- fused pre-pass: feats transpose + xyz pack (job by blockIdx.x) ----
__global__ __launch_bounds__(256) void prepass_kernel(
    const float* __restrict__ xyz, const float* __restrict__ feats)
{
    if (blockIdx.x < TBLOCKS) {
        // transpose (B,C,N) -> (B,N,C), one 32-point x 64-channel tile
        __shared__ float tile[32][65];
        const int b  = blockIdx.x >> 9;          // / (NPTS/32)
        const int n0 = (blockIdx.x & 511) * 32;
        const int t  = threadIdx.x;
        const int tx = t & 31;                   // n within tile
        const int ty = t >> 5;                   // c base (0..7)

        const float* src = feats + (size_t)b * NC * NPTS + n0;
        #pragma unroll
        for (int k = 0; k < 8; ++k) {
            const int c = ty * 8 + k;
            tile[tx][c] = src[(size_t)c * NPTS + tx];
        }
        __syncthreads();

        float* dst = g_feats_t + ((size_t)b * NPTS + n0) * NC;
        #pragma unroll
        for (int k = 0; k < 8; ++k) {
            const int idx = k * 256 + t;
            const int n = idx >> 6;
            const int c = idx & 63;
            dst[(size_t)n * NC + c] = tile[n][c];
        }
    } else {
        // pack (B,N,3) f32 -> (B,N) float4
        __shared__ float sbuf[8][96];
        const int bid  = blockIdx.x - TBLOCKS;
        const int warp = threadIdx.x >> 5, lane = threadIdx.x & 31;
        const size_t base = (size_t)bid * 256 + warp * 32;
        const float* src = xyz + base * 3;
        float* s = sbuf[warp];
        s[lane]      = src[lane];
        s[lane + 32] = src[lane + 32];
        s[lane + 64] = src[lane + 64];
        __syncwarp();
        g_xyz4[base + lane] = make_float4(s[lane * 3], s[lane * 3 + 1], s[lane * 3 + 2], 0.f);
    }
}

// ---- main: 8x-unrolled ball-query scan + float4 grouped gather ----
__global__ __launch_bounds__(WPB * 32) void qag_kernel(
    const float* __restrict__ new_xyz,  // (B, S, 3)
    float* __restrict__ out)            // (B, 3+C, S, NS)
{
    const int lane = threadIdx.x & 31;
    const int wid  = threadIdx.x >> 5;
    const int q = blockIdx.x * WPB + wid;      // global query id in [0, B*S)
    const int b = q >> 10;                     // / NQ
    const int s = q & (NQ - 1);

    // 288 slots: 32 needed + 256 slack (max overshoot within the final chunk)
    // lets the hot loop skip the pos<NS bounds check entirely.
    __shared__ int idx_buf_all[WPB][NS + 256];
    int* idx_buf = idx_buf_all[wid];

    const float qx = new_xyz[q * 3 + 0];
    const float qy = new_xyz[q * 3 + 1];
    const float qz = new_xyz[q * 3 + 2];

    const float4* __restrict__ xb4 = g_xyz4 + (size_t)b * NPTS;
    const unsigned lt = (1u << lane) - 1u;

    // ---- ball query: chunks of 256 points, MLP=8, early exit per chunk ----
    int cnt = 0;
    for (int j0 = 0; j0 < NPTS; j0 += 256) {
        float4 p[8];
        #pragma unroll
        for (int u = 0; u < 8; ++u) p[u] = xb4[j0 + u * 32 + lane];

        bool w[8];
        #pragma unroll
        for (int u = 0; u < 8; ++u) {
            const float dx = p[u].x - qx;
            const float dy = p[u].y - qy;
            const float dz = p[u].z - qz;
            w[u] = dx * dx + dy * dy + dz * dz < R2;
        }

        unsigned m[8];
        #pragma unroll
        for (int u = 0; u < 8; ++u) m[u] = __ballot_sync(0xFFFFFFFFu, w[u]);

        int base = cnt;
        #pragma unroll
        for (int u = 0; u < 8; ++u) {
            if (w[u]) idx_buf[base + __popc(m[u] & lt)] = j0 + u * 32 + lane;
            base += __popc(m[u]);
        }
        cnt = base;
        if (cnt >= NS) break;   // uniform across warp
    }
    __syncwarp();
    const int eff = cnt < NS ? cnt : NS;
    int first = 0;
    if (eff > 0) first = idx_buf[0];
    __syncwarp();
    if (lane >= eff) idx_buf[lane] = first;   // pad with first valid (0 if none)
    __syncwarp();
    const int my = idx_buf[lane];             // lane k owns sample k

    // ---- grouped xyz (channels 0..2), coalesced writes ----
    const float4 P = xb4[my];
    const size_t CH = (size_t)NQ * NS;                         // channel stride
    float* ob = out + ((size_t)b * (3 + NC) * NQ + s) * NS + lane;
    ob[0 * CH] = P.x - qx;
    ob[1 * CH] = P.y - qy;
    ob[2 * CH] = P.z - qz;

    // ---- grouped features: float4 row gather, lane = sample, MLP=8 ----
    const float4* __restrict__ fb =
        (const float4*)(g_feats_t + (size_t)b * NPTS * NC) + (size_t)my * (NC / 4);
    float* of = ob + 3 * CH;
    #pragma unroll
    for (int half = 0; half < 2; ++half) {
        float4 v[8];
        #pragma unroll
        for (int g = 0; g < 8; ++g) v[g] = __ldg(fb + half * 8 + g);
        #pragma unroll
        for (int g = 0; g < 8; ++g) {
            const int c = (half * 8 + g) * 4;
            of[(size_t)(c + 0) * CH] = v[g].x;
            of[(size_t)(c + 1) * CH] = v[g].y;
            of[(size_t)(c + 2) * CH] = v[g].z;
            of[(size_t)(c + 3) * CH] = v[g].w;
        }
    }
}

extern "C" void kernel_launch(void* const* d_in, const int* in_sizes, int n_in,
                              void* d_out, int out_size) {
    const float* xyz     = (const float*)d_in[0];
    const float* new_xyz = (const float*)d_in[1];
    const float* feats   = (const float*)d_in[2];
    float* out = (float*)d_out;

    prepass_kernel<<<TBLOCKS + PBLOCKS, 256>>>(xyz, feats);

    const int nq = NB * NQ;                 // 8192 queries, one warp each
    qag_kernel<<<nq / WPB, WPB * 32>>>(new_xyz, out);
}